// round 2
// baseline (speedup 1.0000x reference)
#include <cuda_runtime.h>
#include <cuda_bf16.h>
#include <cstdint>

// Problem constants
#define BATCH   8192
#define DMODEL  768
#define DSAE    24576
#define TOPK    32

// ---------------------------------------------------------------------------
// Scratch (static __device__ globals; no allocation allowed)
// ---------------------------------------------------------------------------
__device__ float g_preact[(size_t)BATCH * DSAE];     // 768 MB
__device__ float g_wdecT[(size_t)DSAE * DMODEL];     // 72 MB  (W_dec transposed)
__device__ int   g_topk_idx[BATCH * TOPK];
__device__ float g_topk_val[BATCH * TOPK];

// ---------------------------------------------------------------------------
// Kernel 1: fp32 SIMT GEMM  pre_act[b,s] = sum_d x[b,d]*W_enc[s,d] + b_enc[s]
// M=BATCH, N=DSAE, K=DMODEL. Tiles: 128x128x16, 256 threads, 8x8 per thread.
// ---------------------------------------------------------------------------
#define GBM 128
#define GBN 128
#define GBK 16

__global__ __launch_bounds__(256, 1)
void sae_encoder_gemm(const float* __restrict__ x,
                      const float* __restrict__ Wenc,
                      const float* __restrict__ benc)
{
    __shared__ float As[GBK][GBM];   // As[k][m] = x[m0+m][kt+k]
    __shared__ float Bs[GBK][GBN];   // Bs[k][n] = Wenc[n0+n][kt+k]

    const int tid = threadIdx.x;
    const int tx  = tid & 15;        // n sub-tile
    const int ty  = tid >> 4;        // m sub-tile
    const int n0  = blockIdx.x * GBN;
    const int m0  = blockIdx.y * GBM;

    float acc[8][8];
#pragma unroll
    for (int i = 0; i < 8; ++i)
#pragma unroll
        for (int j = 0; j < 8; ++j) acc[i][j] = 0.0f;

    for (int kt = 0; kt < DMODEL; kt += GBK) {
        // Load A tile: 128 rows x 16 cols = 512 float4, 2 per thread
#pragma unroll
        for (int q = 0; q < 2; ++q) {
            int idx = tid * 2 + q;          // 0..511
            int mi  = idx >> 2;             // row in tile
            int kc  = idx & 3;              // float4 chunk in k
            const float4 av = *reinterpret_cast<const float4*>(
                x + (size_t)(m0 + mi) * DMODEL + kt + kc * 4);
            As[kc * 4 + 0][mi] = av.x;
            As[kc * 4 + 1][mi] = av.y;
            As[kc * 4 + 2][mi] = av.z;
            As[kc * 4 + 3][mi] = av.w;
        }
        // Load B tile: 128 s-rows x 16 cols
#pragma unroll
        for (int q = 0; q < 2; ++q) {
            int idx = tid * 2 + q;
            int si  = idx >> 2;
            int kc  = idx & 3;
            const float4 bv = *reinterpret_cast<const float4*>(
                Wenc + (size_t)(n0 + si) * DMODEL + kt + kc * 4);
            Bs[kc * 4 + 0][si] = bv.x;
            Bs[kc * 4 + 1][si] = bv.y;
            Bs[kc * 4 + 2][si] = bv.z;
            Bs[kc * 4 + 3][si] = bv.w;
        }
        __syncthreads();

#pragma unroll
        for (int k = 0; k < GBK; ++k) {
            float a[8], b[8];
#pragma unroll
            for (int i = 0; i < 8; ++i) a[i] = As[k][ty * 8 + i];
#pragma unroll
            for (int j = 0; j < 8; ++j) b[j] = Bs[k][tx * 8 + j];
#pragma unroll
            for (int i = 0; i < 8; ++i)
#pragma unroll
                for (int j = 0; j < 8; ++j)
                    acc[i][j] = fmaf(a[i], b[j], acc[i][j]);
        }
        __syncthreads();
    }

    // Epilogue: + bias, store
    float bias[8];
#pragma unroll
    for (int j = 0; j < 8; ++j) bias[j] = benc[n0 + tx * 8 + j];

#pragma unroll
    for (int i = 0; i < 8; ++i) {
        const size_t crow = (size_t)(m0 + ty * 8 + i) * DSAE + n0 + tx * 8;
        float4 v0, v1;
        v0.x = acc[i][0] + bias[0];
        v0.y = acc[i][1] + bias[1];
        v0.z = acc[i][2] + bias[2];
        v0.w = acc[i][3] + bias[3];
        v1.x = acc[i][4] + bias[4];
        v1.y = acc[i][5] + bias[5];
        v1.z = acc[i][6] + bias[6];
        v1.w = acc[i][7] + bias[7];
        *reinterpret_cast<float4*>(g_preact + crow)     = v0;
        *reinterpret_cast<float4*>(g_preact + crow + 4) = v1;
    }
}

// ---------------------------------------------------------------------------
// Kernel 2: per-row exact top-32 via 4-level (byte) radix select on
// order-preserving uint keys, then scatter into dense latents + compact lists.
// One block (256 threads) per row.
// ---------------------------------------------------------------------------
__device__ __forceinline__ unsigned fkey(float f) {
    unsigned u = __float_as_uint(f);
    return (u & 0x80000000u) ? ~u : (u | 0x80000000u);
}

__global__ __launch_bounds__(256, 4)
void sae_topk(float* __restrict__ latents)
{
    const int row = blockIdx.x;
    const int tid = threadIdx.x;
    const float* __restrict__ p = g_preact + (size_t)row * DSAE;

    __shared__ unsigned hist[256];
    __shared__ unsigned s_pref;
    __shared__ int      s_rem;
    __shared__ int      s_cnt;
    __shared__ int      s_eq;

    if (tid == 0) { s_pref = 0u; s_rem = TOPK; }
    __syncthreads();

    for (int lv = 3; lv >= 0; --lv) {
        hist[tid] = 0u;
        __syncthreads();
        const unsigned prefHi = (lv == 3) ? 0u : (s_pref >> ((lv + 1) * 8));
        const int shift = lv * 8;
        for (int i = tid; i < DSAE; i += 256) {
            unsigned key = fkey(p[i]);
            bool ok = (lv == 3) || ((key >> ((lv + 1) * 8)) == prefHi);
            if (ok) atomicAdd(&hist[(key >> shift) & 255u], 1u);
        }
        __syncthreads();
        if (tid == 0) {
            int rem = s_rem;
            unsigned cum = 0;
            for (int b = 255; b >= 0; --b) {
                cum += hist[b];
                if ((int)cum >= rem) {
                    s_pref |= ((unsigned)b) << shift;
                    s_rem   = rem - (int)(cum - hist[b]);
                    break;
                }
            }
        }
        __syncthreads();
    }

    const unsigned T = s_pref;       // key of the 32nd-largest element
    const int needEq = s_rem;        // how many elements equal to T we take
    if (tid == 0) { s_cnt = 0; s_eq = 0; }
    __syncthreads();

    for (int i = tid; i < DSAE; i += 256) {
        float v = p[i];
        unsigned key = fkey(v);
        if (key > T) {
            int slot = atomicAdd(&s_cnt, 1);
            g_topk_idx[row * TOPK + slot] = i;
            g_topk_val[row * TOPK + slot] = v;
            latents[(size_t)row * DSAE + i] = v;
        } else if (key == T) {
            int e = atomicAdd(&s_eq, 1);
            if (e < needEq) {
                int slot = atomicAdd(&s_cnt, 1);
                g_topk_idx[row * TOPK + slot] = i;
                g_topk_val[row * TOPK + slot] = v;
                latents[(size_t)row * DSAE + i] = v;
            }
        }
    }
}

// ---------------------------------------------------------------------------
// Kernel 3: transpose W_dec [DMODEL, DSAE] -> g_wdecT [DSAE, DMODEL]
// ---------------------------------------------------------------------------
__global__ __launch_bounds__(256, 4)
void sae_transpose_wdec(const float* __restrict__ Wdec)
{
    __shared__ float t[32][33];
    const int tx = threadIdx.x;      // 0..31
    const int ty = threadIdx.y;      // 0..7
    const int s0 = blockIdx.x * 32;  // DSAE tile (cols of Wdec)
    const int m0 = blockIdx.y * 32;  // DMODEL tile (rows of Wdec)

#pragma unroll
    for (int j = 0; j < 4; ++j) {
        int m = m0 + ty + j * 8;
        t[ty + j * 8][tx] = Wdec[(size_t)m * DSAE + s0 + tx];
    }
    __syncthreads();
#pragma unroll
    for (int j = 0; j < 4; ++j) {
        int s = s0 + ty + j * 8;
        g_wdecT[(size_t)s * DMODEL + m0 + tx] = t[tx][ty + j * 8];
    }
}

// ---------------------------------------------------------------------------
// Kernel 4: sparse decode  recon[b,m] = sum_k val_k * WdecT[idx_k][m]
// One block per row, 256 threads; each thread owns 3 m positions.
// ---------------------------------------------------------------------------
__global__ __launch_bounds__(256, 4)
void sae_decode(float* __restrict__ recon)
{
    const int row = blockIdx.x;
    const int tid = threadIdx.x;

    __shared__ int   sidx[TOPK];
    __shared__ float sval[TOPK];
    if (tid < TOPK) {
        sidx[tid] = g_topk_idx[row * TOPK + tid];
        sval[tid] = g_topk_val[row * TOPK + tid];
    }
    __syncthreads();

    float a0 = 0.0f, a1 = 0.0f, a2 = 0.0f;
#pragma unroll 8
    for (int k = 0; k < TOPK; ++k) {
        const float v = sval[k];
        const float* __restrict__ wr = g_wdecT + (size_t)sidx[k] * DMODEL;
        a0 = fmaf(v, wr[tid],       a0);
        a1 = fmaf(v, wr[tid + 256], a1);
        a2 = fmaf(v, wr[tid + 512], a2);
    }
    float* __restrict__ r = recon + (size_t)row * DMODEL;
    r[tid]       = a0;
    r[tid + 256] = a1;
    r[tid + 512] = a2;
}

// ---------------------------------------------------------------------------
// Launch
// ---------------------------------------------------------------------------
extern "C" void kernel_launch(void* const* d_in, const int* in_sizes, int n_in,
                              void* d_out, int out_size)
{
    const float* x     = (const float*)d_in[0];   // [8192, 768]
    const float* Wenc  = (const float*)d_in[1];   // [24576, 768]
    const float* benc  = (const float*)d_in[2];   // [24576]
    const float* Wdec  = (const float*)d_in[3];   // [768, 24576]

    float* out     = (float*)d_out;
    float* recon   = out;                                   // [8192, 768]
    float* latents = out + (size_t)BATCH * DMODEL;          // [8192, 24576]

    // Zero the dense latents region (scatter target).
    cudaMemsetAsync(latents, 0, (size_t)BATCH * DSAE * sizeof(float), 0);

    // Transpose W_dec (independent of GEMM; ordered on same stream).
    sae_transpose_wdec<<<dim3(DSAE / 32, DMODEL / 32), dim3(32, 8)>>>(Wdec);

    // Encoder GEMM -> g_preact
    sae_encoder_gemm<<<dim3(DSAE / GBN, BATCH / GBM), 256>>>(x, Wenc, benc);

    // Per-row exact top-32 + scatter
    sae_topk<<<BATCH, 256>>>(latents);

    // Sparse decode -> recon
    sae_decode<<<BATCH, 256>>>(recon);
}

// round 4
// speedup vs baseline: 2.6157x; 2.6157x over previous
#include <cuda_runtime.h>
#include <cuda_bf16.h>
#include <cstdint>

// Problem constants
#define BATCH   8192
#define DMODEL  768
#define DSAE    24576
#define TOPK    32

#define CAND_TH   2.0f
#define CAND_MAX  1024
#define REFINE_K  64

// ---------------------------------------------------------------------------
// Scratch (static __device__ globals; no allocation allowed)
// ---------------------------------------------------------------------------
__device__ __nv_bfloat16 g_xb[(size_t)BATCH * DMODEL];   // 12.6 MB
__device__ __nv_bfloat16 g_wb[(size_t)DSAE * DMODEL];    // 37.7 MB
__device__ float g_wdecT[(size_t)DSAE * DMODEL];         // 72 MB
__device__ int   g_cand_cnt[BATCH];
__device__ int   g_cand_idx[(size_t)BATCH * CAND_MAX];   // 33.5 MB
__device__ float g_cand_val[(size_t)BATCH * CAND_MAX];   // 33.5 MB
__device__ int   g_topk_idx[BATCH * TOPK];
__device__ float g_topk_val[BATCH * TOPK];

// ---------------------------------------------------------------------------
// PTX helpers (baseline ISA only: cp.async / ldmatrix / mma.sync)
// ---------------------------------------------------------------------------
__device__ __forceinline__ uint32_t smem_to_u32(const void* p) {
    uint32_t a;
    asm("{ .reg .u64 t; cvta.to.shared.u64 t, %1; cvt.u32.u64 %0, t; }" : "=r"(a) : "l"(p));
    return a;
}
#define CP_ASYNC16(s, g) \
    asm volatile("cp.async.cg.shared.global [%0], [%1], 16;" :: "r"(s), "l"(g))
#define CP_COMMIT()  asm volatile("cp.async.commit_group;" ::: "memory")
#define CP_WAIT(n)   asm volatile("cp.async.wait_group %0;" :: "n"(n) : "memory")

__device__ __forceinline__ void ldsm_x4(uint32_t addr, uint32_t& r0, uint32_t& r1,
                                        uint32_t& r2, uint32_t& r3)
{
    asm volatile("ldmatrix.sync.aligned.m8n8.x4.shared.b16 {%0,%1,%2,%3}, [%4];"
                 : "=r"(r0), "=r"(r1), "=r"(r2), "=r"(r3) : "r"(addr));
}
__device__ __forceinline__ void mma16816(float& d0, float& d1, float& d2, float& d3,
                                         uint32_t a0, uint32_t a1, uint32_t a2, uint32_t a3,
                                         uint32_t b0, uint32_t b1)
{
    asm volatile(
        "mma.sync.aligned.m16n8k16.row.col.f32.bf16.bf16.f32 "
        "{%0,%1,%2,%3}, {%4,%5,%6,%7}, {%8,%9}, {%0,%1,%2,%3};"
        : "+f"(d0), "+f"(d1), "+f"(d2), "+f"(d3)
        : "r"(a0), "r"(a1), "r"(a2), "r"(a3), "r"(b0), "r"(b1));
}

// ---------------------------------------------------------------------------
// Conversion / zero kernels
// ---------------------------------------------------------------------------
__global__ void conv_to_bf16(const float* __restrict__ src, __nv_bfloat16* __restrict__ dst,
                             size_t n)
{
    size_t i = (size_t)blockIdx.x * blockDim.x + threadIdx.x;
    size_t stride = (size_t)gridDim.x * blockDim.x;
    for (; i < n; i += stride) dst[i] = __float2bfloat16(src[i]);
}
__global__ void zero_counts()
{
    int i = blockIdx.x * blockDim.x + threadIdx.x;
    if (i < BATCH) g_cand_cnt[i] = 0;
}

// ---------------------------------------------------------------------------
// bf16 HMMA GEMM with fused candidate extraction.
// Block tile 256(M) x 128(N), K-chunks of 64. 512 threads = 16 warps (8M x 2N),
// warp tile 32x64 -> 2x8 m16n8k16 mmas. 2-stage cp.async pipeline, SW128 smem.
// ---------------------------------------------------------------------------
#define BM 256
#define BN 128
#define BK 64
#define NCHUNKS (DMODEL / BK)          // 12
#define A_STAGE_BYTES (BM * 128)       // 32 KB
#define B_STAGE_BYTES (BN * 128)       // 16 KB
#define SMEM_GEMM_BYTES (2 * A_STAGE_BYTES + 2 * B_STAGE_BYTES)   // 96 KB

__device__ __forceinline__ void push_cand(int row, int col, float v)
{
    if (v > CAND_TH) {
        int pos = atomicAdd(&g_cand_cnt[row], 1);
        if (pos < CAND_MAX) {
            g_cand_idx[(size_t)row * CAND_MAX + pos] = col;
            g_cand_val[(size_t)row * CAND_MAX + pos] = v;
        }
    }
}

__global__ void __launch_bounds__(512)
sae_gemm_bf16(const __nv_bfloat16* __restrict__ xb,
              const __nv_bfloat16* __restrict__ wb,
              const float* __restrict__ benc)
{
    extern __shared__ __align__(1024) char smem[];
    const uint32_t sb = smem_to_u32(smem);

    const int tid  = threadIdx.x;
    const int wid  = tid >> 5;
    const int lane = tid & 31;
    const int wm   = wid & 7;          // 0..7 (M)
    const int wn   = wid >> 3;         // 0..1 (N)
    const int n0   = blockIdx.x * BN;
    const int m0   = blockIdx.y * BM;

    const char* gA = (const char*)xb + (size_t)m0 * (DMODEL * 2);
    const char* gB = (const char*)wb + (size_t)n0 * (DMODEL * 2);

    float acc[2][8][4];
#pragma unroll
    for (int i = 0; i < 2; ++i)
#pragma unroll
        for (int j = 0; j < 8; ++j)
#pragma unroll
            for (int q = 0; q < 4; ++q) acc[i][j][q] = 0.0f;

    // ---- async tile loader (chunk c -> stage st) ----
    auto load_tiles = [&](int c, int st) {
        const int ktb = c * (BK * 2);            // k byte offset in gmem row
        const uint32_t sa = sb + st * A_STAGE_BYTES;
        const uint32_t sB = sb + 2 * A_STAGE_BYTES + st * B_STAGE_BYTES;
        // A: 256 rows x 8 chunks of 16B
#pragma unroll
        for (int q = 0; q < 4; ++q) {
            int i = tid + q * 512;               // 0..2047
            int row = i >> 3, cc = i & 7;
            uint32_t soff = (uint32_t)(row * 128 + ((cc ^ (row & 7)) << 4));
            CP_ASYNC16(sa + soff, gA + (size_t)row * (DMODEL * 2) + ktb + cc * 16);
        }
        // B: 128 rows x 8 chunks
#pragma unroll
        for (int q = 0; q < 2; ++q) {
            int i = tid + q * 512;               // 0..1023
            int row = i >> 3, cc = i & 7;
            uint32_t soff = (uint32_t)(row * 128 + ((cc ^ (row & 7)) << 4));
            CP_ASYNC16(sB + soff, gB + (size_t)row * (DMODEL * 2) + ktb + cc * 16);
        }
    };

    // prologue
    load_tiles(0, 0);
    CP_COMMIT();

    for (int c = 0; c < NCHUNKS; ++c) {
        const int st = c & 1;
        if (c + 1 < NCHUNKS) {
            load_tiles(c + 1, (c + 1) & 1);
            CP_COMMIT();
            CP_WAIT(1);
        } else {
            CP_WAIT(0);
        }
        __syncthreads();

        const uint32_t sa = sb + st * A_STAGE_BYTES;
        const uint32_t sB = sb + 2 * A_STAGE_BYTES + st * B_STAGE_BYTES;

#pragma unroll
        for (int ks = 0; ks < 4; ++ks) {         // 4 x k16 per 64-chunk
            uint32_t a[2][4];
#pragma unroll
            for (int mt = 0; mt < 2; ++mt) {
                int m = wm * 32 + mt * 16 + (lane & 15);
                int chunk = 2 * ks + (lane >> 4);
                uint32_t addr = sa + (uint32_t)(m * 128 + ((chunk ^ (m & 7)) << 4));
                ldsm_x4(addr, a[mt][0], a[mt][1], a[mt][2], a[mt][3]);
            }
            uint32_t b[8][2];
#pragma unroll
            for (int p = 0; p < 4; ++p) {        // each x4 covers two n8 tiles
                int n = wn * 64 + p * 16 + (lane & 15);
                int chunk = 2 * ks + (lane >> 4);
                uint32_t addr = sB + (uint32_t)(n * 128 + ((chunk ^ (n & 7)) << 4));
                uint32_t r0, r1, r2, r3;
                ldsm_x4(addr, r0, r1, r2, r3);
                b[2 * p][0] = r0; b[2 * p + 1][0] = r1;
                b[2 * p][1] = r2; b[2 * p + 1][1] = r3;
            }
#pragma unroll
            for (int mt = 0; mt < 2; ++mt)
#pragma unroll
                for (int nt = 0; nt < 8; ++nt)
                    mma16816(acc[mt][nt][0], acc[mt][nt][1], acc[mt][nt][2], acc[mt][nt][3],
                             a[mt][0], a[mt][1], a[mt][2], a[mt][3],
                             b[nt][0], b[nt][1]);
        }
        __syncthreads();
    }

    // ---- epilogue: bias + candidate extraction straight from registers ----
#pragma unroll
    for (int mt = 0; mt < 2; ++mt) {
        const int r0 = m0 + wm * 32 + mt * 16 + (lane >> 2);
        const int r1 = r0 + 8;
#pragma unroll
        for (int nt = 0; nt < 8; ++nt) {
            const int cA = n0 + wn * 64 + nt * 8 + 2 * (lane & 3);
            const float bA = __ldg(benc + cA);
            const float bB = __ldg(benc + cA + 1);
            push_cand(r0, cA,     acc[mt][nt][0] + bA);
            push_cand(r0, cA + 1, acc[mt][nt][1] + bB);
            push_cand(r1, cA,     acc[mt][nt][2] + bA);
            push_cand(r1, cA + 1, acc[mt][nt][3] + bB);
        }
    }
}

// ---------------------------------------------------------------------------
// Block-wide radix select helpers
// ---------------------------------------------------------------------------
__device__ __forceinline__ unsigned fkey(float f) {
    unsigned u = __float_as_uint(f);
    return (u & 0x80000000u) ? ~u : (u | 0x80000000u);
}

__device__ void radix_select_smem(const float* vals, int n, int k,
                                  unsigned* hist, unsigned* prefp, int* remp)
{
    const int tid = threadIdx.x;
    const int nth = blockDim.x;
    if (tid == 0) { *prefp = 0u; *remp = k; }
    __syncthreads();
    for (int lv = 3; lv >= 0; --lv) {
        for (int b = tid; b < 256; b += nth) hist[b] = 0u;
        __syncthreads();
        const unsigned pref = *prefp;
        const unsigned prefHi = (lv == 3) ? 0u : (pref >> ((lv + 1) * 8));
        const int shift = lv * 8;
        for (int i = tid; i < n; i += nth) {
            unsigned key = fkey(vals[i]);
            bool ok = (lv == 3) || ((key >> ((lv + 1) * 8)) == prefHi);
            if (ok) atomicAdd(&hist[(key >> shift) & 255u], 1u);
        }
        __syncthreads();
        if (tid == 0) {
            int rem = *remp;
            unsigned cum = 0;
            for (int b = 255; b >= 0; --b) {
                cum += hist[b];
                if ((int)cum >= rem) {
                    *prefp = pref | ((unsigned)b << shift);
                    *remp = rem - (int)(cum - hist[b]);
                    break;
                }
            }
        }
        __syncthreads();
    }
}

// ---------------------------------------------------------------------------
// Per-row: approx-top-64 among candidates -> exact fp32 recompute -> exact
// top-32 -> scatter into latents + compact topk lists. One block per row.
// ---------------------------------------------------------------------------
__global__ void __launch_bounds__(256)
sae_select(const float* __restrict__ x,
           const float* __restrict__ Wenc,
           const float* __restrict__ benc,
           float* __restrict__ latents)
{
    const int row = blockIdx.x;
    const int tid = threadIdx.x;
    const int wid = tid >> 5;
    const int lid = tid & 31;

    __shared__ float sval[CAND_MAX];
    __shared__ int   sidx[CAND_MAX];
    __shared__ float sx[DMODEL];
    __shared__ unsigned hist[256];
    __shared__ unsigned s_pref;
    __shared__ int s_rem, s_cnt, s_eq, s_taken;
    __shared__ int   sel_idx[REFINE_K];
    __shared__ float sel_val[REFINE_K];

    int cnt = g_cand_cnt[row];
    if (cnt > CAND_MAX) cnt = CAND_MAX;

    for (int i = tid; i < cnt; i += 256) {
        sval[i] = g_cand_val[(size_t)row * CAND_MAX + i];
        sidx[i] = g_cand_idx[(size_t)row * CAND_MAX + i];
    }
    for (int i = tid; i < DMODEL; i += 256) sx[i] = x[(size_t)row * DMODEL + i];
    __syncthreads();

    // --- Stage 1: approx top-K1 by bf16-GEMM value ---
    int K1 = (cnt < REFINE_K) ? cnt : REFINE_K;
    if (K1 > 0) radix_select_smem(sval, cnt, K1, hist, &s_pref, &s_rem);
    if (tid == 0) { s_cnt = 0; s_eq = 0; }
    __syncthreads();
    if (K1 > 0) {
        const unsigned T = s_pref;
        const int needEq = s_rem;
        for (int i = tid; i < cnt; i += 256) {
            unsigned key = fkey(sval[i]);
            if (key > T) {
                int slot = atomicAdd(&s_cnt, 1);
                sel_idx[slot] = sidx[i];
            } else if (key == T) {
                int e = atomicAdd(&s_eq, 1);
                if (e < needEq) {
                    int slot = atomicAdd(&s_cnt, 1);
                    sel_idx[slot] = sidx[i];
                }
            }
        }
    }
    __syncthreads();

    // --- Stage 2: exact fp32 recompute of the K1 selected candidates ---
    for (int j = wid; j < K1; j += 8) {
        const int s = sel_idx[j];
        const float* __restrict__ wr = Wenc + (size_t)s * DMODEL;
        float a = 0.0f;
#pragma unroll 6
        for (int kk = lid; kk < DMODEL; kk += 32)
            a = fmaf(sx[kk], wr[kk], a);
#pragma unroll
        for (int o = 16; o; o >>= 1) a += __shfl_xor_sync(0xFFFFFFFFu, a, o);
        if (lid == 0) sel_val[j] = a + benc[s];
    }
    __syncthreads();

    // --- Stage 3: exact top-32 among the K1 exact values ---
    int K2 = (K1 < TOPK) ? K1 : TOPK;
    if (K2 > 0) radix_select_smem(sel_val, K1, K2, hist, &s_pref, &s_rem);
    if (tid == 0) { s_taken = 0; s_eq = 0; }
    __syncthreads();
    if (K2 > 0) {
        const unsigned T2 = s_pref;
        const int needEq2 = s_rem;
        for (int i = tid; i < K1; i += 256) {
            float v = sel_val[i];
            unsigned key = fkey(v);
            bool take = false;
            if (key > T2) take = true;
            else if (key == T2) {
                int e = atomicAdd(&s_eq, 1);
                if (e < needEq2) take = true;
            }
            if (take) {
                int slot = atomicAdd(&s_taken, 1);
                int col = sel_idx[i];
                g_topk_idx[row * TOPK + slot] = col;
                g_topk_val[row * TOPK + slot] = v;
                latents[(size_t)row * DSAE + col] = v;
            }
        }
    }
    __syncthreads();
    if (tid >= s_taken && tid < TOPK) {      // defensive tail fill
        g_topk_idx[row * TOPK + tid] = 0;
        g_topk_val[row * TOPK + tid] = 0.0f;
    }
}

// ---------------------------------------------------------------------------
// Transpose W_dec [DMODEL, DSAE] -> g_wdecT [DSAE, DMODEL]
// ---------------------------------------------------------------------------
__global__ __launch_bounds__(256, 4)
void sae_transpose_wdec(const float* __restrict__ Wdec)
{
    __shared__ float t[32][33];
    const int tx = threadIdx.x;
    const int ty = threadIdx.y;
    const int s0 = blockIdx.x * 32;
    const int m0 = blockIdx.y * 32;

#pragma unroll
    for (int j = 0; j < 4; ++j) {
        int m = m0 + ty + j * 8;
        t[ty + j * 8][tx] = Wdec[(size_t)m * DSAE + s0 + tx];
    }
    __syncthreads();
#pragma unroll
    for (int j = 0; j < 4; ++j) {
        int s = s0 + ty + j * 8;
        g_wdecT[(size_t)s * DMODEL + m0 + tx] = t[tx][ty + j * 8];
    }
}

// ---------------------------------------------------------------------------
// Sparse decode: recon[b,m] = sum_k val_k * WdecT[idx_k][m]
// ---------------------------------------------------------------------------
__global__ __launch_bounds__(256, 4)
void sae_decode(float* __restrict__ recon)
{
    const int row = blockIdx.x;
    const int tid = threadIdx.x;

    __shared__ int   sidx[TOPK];
    __shared__ float sv[TOPK];
    if (tid < TOPK) {
        sidx[tid] = g_topk_idx[row * TOPK + tid];
        sv[tid]   = g_topk_val[row * TOPK + tid];
    }
    __syncthreads();

    float a0 = 0.0f, a1 = 0.0f, a2 = 0.0f;
#pragma unroll 8
    for (int k = 0; k < TOPK; ++k) {
        const float v = sv[k];
        const float* __restrict__ wr = g_wdecT + (size_t)sidx[k] * DMODEL;
        a0 = fmaf(v, wr[tid],       a0);
        a1 = fmaf(v, wr[tid + 256], a1);
        a2 = fmaf(v, wr[tid + 512], a2);
    }
    float* __restrict__ r = recon + (size_t)row * DMODEL;
    r[tid]       = a0;
    r[tid + 256] = a1;
    r[tid + 512] = a2;
}

// ---------------------------------------------------------------------------
// Launch
// ---------------------------------------------------------------------------
extern "C" void kernel_launch(void* const* d_in, const int* in_sizes, int n_in,
                              void* d_out, int out_size)
{
    const float* x    = (const float*)d_in[0];   // [8192, 768]
    const float* Wenc = (const float*)d_in[1];   // [24576, 768]
    const float* benc = (const float*)d_in[2];   // [24576]
    const float* Wdec = (const float*)d_in[3];   // [768, 24576]

    float* out     = (float*)d_out;
    float* recon   = out;
    float* latents = out + (size_t)BATCH * DMODEL;

    cudaFuncSetAttribute(sae_gemm_bf16, cudaFuncAttributeMaxDynamicSharedMemorySize,
                         SMEM_GEMM_BYTES);

    __nv_bfloat16 *xb_p = nullptr, *wb_p = nullptr;
    cudaGetSymbolAddress((void**)&xb_p, g_xb);
    cudaGetSymbolAddress((void**)&wb_p, g_wb);

    // 0) conversions + counter zero + W_dec transpose
    conv_to_bf16<<<4096, 256>>>(x, xb_p, (size_t)BATCH * DMODEL);
    conv_to_bf16<<<8192, 256>>>(Wenc, wb_p, (size_t)DSAE * DMODEL);
    zero_counts<<<BATCH / 256, 256>>>();
    sae_transpose_wdec<<<dim3(DSAE / 32, DMODEL / 32), dim3(32, 8)>>>(Wdec);

    // 1) bf16 HMMA GEMM with fused candidate extraction
    sae_gemm_bf16<<<dim3(DSAE / BN, BATCH / BM), 512, SMEM_GEMM_BYTES>>>(xb_p, wb_p, benc);

    // 2) zero dense latents, then exact select + scatter
    cudaMemsetAsync(latents, 0, (size_t)BATCH * DSAE * sizeof(float), 0);
    sae_select<<<BATCH, 256>>>(x, Wenc, benc, latents);

    // 3) sparse decode
    sae_decode<<<BATCH, 256>>>(recon);
}

// round 5
// speedup vs baseline: 3.2166x; 1.2297x over previous
#include <cuda_runtime.h>
#include <cuda_bf16.h>
#include <cstdint>

// Problem constants
#define BATCH   8192
#define DMODEL  768
#define DSAE    24576
#define TOPK    32

#define CAND_TH   2.0f
#define CAND_MAX  1024
#define REFINE_K  64

// ---------------------------------------------------------------------------
// Scratch (static __device__ globals; no allocation allowed)
// ---------------------------------------------------------------------------
__device__ __nv_bfloat16 g_xb[(size_t)BATCH * DMODEL];   // 12.6 MB
__device__ __nv_bfloat16 g_wb[(size_t)DSAE * DMODEL];    // 37.7 MB
__device__ float g_wdecT[(size_t)DSAE * DMODEL];         // 72 MB
__device__ int   g_cand_cnt[BATCH];
__device__ int   g_cand_idx[(size_t)BATCH * CAND_MAX];   // 33.5 MB
__device__ float g_cand_val[(size_t)BATCH * CAND_MAX];   // 33.5 MB
__device__ int   g_topk_idx[BATCH * TOPK];
__device__ float g_topk_val[BATCH * TOPK];

// ---------------------------------------------------------------------------
// PTX helpers (baseline ISA only: cp.async / ldmatrix / mma.sync)
// ---------------------------------------------------------------------------
__device__ __forceinline__ uint32_t smem_to_u32(const void* p) {
    uint32_t a;
    asm("{ .reg .u64 t; cvta.to.shared.u64 t, %1; cvt.u32.u64 %0, t; }" : "=r"(a) : "l"(p));
    return a;
}
#define CP_ASYNC16(s, g) \
    asm volatile("cp.async.cg.shared.global [%0], [%1], 16;" :: "r"(s), "l"(g))
#define CP_COMMIT()  asm volatile("cp.async.commit_group;" ::: "memory")
#define CP_WAIT(n)   asm volatile("cp.async.wait_group %0;" :: "n"(n) : "memory")

__device__ __forceinline__ void ldsm_x4(uint32_t addr, uint32_t& r0, uint32_t& r1,
                                        uint32_t& r2, uint32_t& r3)
{
    asm volatile("ldmatrix.sync.aligned.m8n8.x4.shared.b16 {%0,%1,%2,%3}, [%4];"
                 : "=r"(r0), "=r"(r1), "=r"(r2), "=r"(r3) : "r"(addr));
}
__device__ __forceinline__ void mma16816(float& d0, float& d1, float& d2, float& d3,
                                         uint32_t a0, uint32_t a1, uint32_t a2, uint32_t a3,
                                         uint32_t b0, uint32_t b1)
{
    asm volatile(
        "mma.sync.aligned.m16n8k16.row.col.f32.bf16.bf16.f32 "
        "{%0,%1,%2,%3}, {%4,%5,%6,%7}, {%8,%9}, {%0,%1,%2,%3};"
        : "+f"(d0), "+f"(d1), "+f"(d2), "+f"(d3)
        : "r"(a0), "r"(a1), "r"(a2), "r"(a3), "r"(b0), "r"(b1));
}

// ---------------------------------------------------------------------------
// Conversion / zero kernels
// ---------------------------------------------------------------------------
__global__ void conv_to_bf16(const float* __restrict__ src, __nv_bfloat16* __restrict__ dst,
                             size_t n)
{
    size_t i = (size_t)blockIdx.x * blockDim.x + threadIdx.x;
    size_t stride = (size_t)gridDim.x * blockDim.x;
    for (; i < n; i += stride) dst[i] = __float2bfloat16(src[i]);
}
__global__ void zero_counts()
{
    int i = blockIdx.x * blockDim.x + threadIdx.x;
    if (i < BATCH) g_cand_cnt[i] = 0;
}

// ---------------------------------------------------------------------------
// bf16 HMMA GEMM with fused candidate extraction + latents zero-fill.
// Block tile 256(M) x 128(N), K-chunks of 64. 256 threads = 8 warps (4M x 2N),
// warp tile 64x64 -> 4x8 m16n8k16 mmas per k16. 3-stage cp.async pipeline.
// ---------------------------------------------------------------------------
#define BM 256
#define BN 128
#define BK 64
#define NCHUNKS (DMODEL / BK)          // 12
#define A_STAGE_BYTES (BM * 128)       // 32 KB
#define B_STAGE_BYTES (BN * 128)       // 16 KB
#define STAGE_BYTES   (A_STAGE_BYTES + B_STAGE_BYTES)   // 48 KB
#define NSTAGES 3
#define SMEM_GEMM_BYTES (NSTAGES * STAGE_BYTES)         // 144 KB

__device__ __forceinline__ void push_cand(int row, int col, float v)
{
    if (v > CAND_TH) {
        int pos = atomicAdd(&g_cand_cnt[row], 1);
        if (pos < CAND_MAX) {
            g_cand_idx[(size_t)row * CAND_MAX + pos] = col;
            g_cand_val[(size_t)row * CAND_MAX + pos] = v;
        }
    }
}

__global__ void __launch_bounds__(256)
sae_gemm_bf16(const __nv_bfloat16* __restrict__ xb,
              const __nv_bfloat16* __restrict__ wb,
              const float* __restrict__ benc,
              float* __restrict__ latents)
{
    extern __shared__ __align__(1024) char smem[];
    const uint32_t sb = smem_to_u32(smem);

    const int tid  = threadIdx.x;
    const int wid  = tid >> 5;
    const int lane = tid & 31;
    const int wm   = wid & 3;          // 0..3 (M, 64 rows each)
    const int wn   = wid >> 2;         // 0..1 (N, 64 cols each)
    const int n0   = blockIdx.x * BN;
    const int m0   = blockIdx.y * BM;

    const char* gA = (const char*)xb + (size_t)m0 * (DMODEL * 2);
    const char* gB = (const char*)wb + (size_t)n0 * (DMODEL * 2);

    float acc[4][8][4];
#pragma unroll
    for (int i = 0; i < 4; ++i)
#pragma unroll
        for (int j = 0; j < 8; ++j)
#pragma unroll
            for (int q = 0; q < 4; ++q) acc[i][j][q] = 0.0f;

    // ---- async tile loader (chunk c -> stage st) ----
    auto load_tiles = [&](int c, int st) {
        const int ktb = c * (BK * 2);            // k byte offset in gmem row
        const uint32_t sa = sb + st * STAGE_BYTES;
        const uint32_t sB = sa + A_STAGE_BYTES;
        // A: 256 rows x 8 chunks of 16B = 2048 -> 8 per thread
#pragma unroll
        for (int q = 0; q < 8; ++q) {
            int i = tid + q * 256;
            int row = i >> 3, cc = i & 7;
            uint32_t soff = (uint32_t)(row * 128 + ((cc ^ (row & 7)) << 4));
            CP_ASYNC16(sa + soff, gA + (size_t)row * (DMODEL * 2) + ktb + cc * 16);
        }
        // B: 128 rows x 8 chunks = 1024 -> 4 per thread
#pragma unroll
        for (int q = 0; q < 4; ++q) {
            int i = tid + q * 256;
            int row = i >> 3, cc = i & 7;
            uint32_t soff = (uint32_t)(row * 128 + ((cc ^ (row & 7)) << 4));
            CP_ASYNC16(sB + soff, gB + (size_t)row * (DMODEL * 2) + ktb + cc * 16);
        }
    };

    // prologue: stages 0,1
    load_tiles(0, 0);
    CP_COMMIT();
    load_tiles(1, 1);
    CP_COMMIT();

    for (int c = 0; c < NCHUNKS; ++c) {
        if (c + 2 < NCHUNKS) {
            load_tiles(c + 2, (c + 2) % NSTAGES);
            CP_COMMIT();
            CP_WAIT(2);
        } else if (c + 2 == NCHUNKS) {
            CP_WAIT(1);
        } else {
            CP_WAIT(0);
        }
        __syncthreads();

        const uint32_t sa = sb + (c % NSTAGES) * STAGE_BYTES;
        const uint32_t sB = sa + A_STAGE_BYTES;

#pragma unroll
        for (int ks = 0; ks < 4; ++ks) {         // 4 x k16 per 64-chunk
            const int chunk = 2 * ks + (lane >> 4);
            uint32_t a[4][4];
#pragma unroll
            for (int mt = 0; mt < 4; ++mt) {
                int m = wm * 64 + mt * 16 + (lane & 15);
                uint32_t addr = sa + (uint32_t)(m * 128 + ((chunk ^ (m & 7)) << 4));
                ldsm_x4(addr, a[mt][0], a[mt][1], a[mt][2], a[mt][3]);
            }
            uint32_t b[8][2];
#pragma unroll
            for (int p = 0; p < 4; ++p) {        // each x4 covers two n8 tiles
                int n = wn * 64 + p * 16 + (lane & 15);
                uint32_t addr = sB + (uint32_t)(n * 128 + ((chunk ^ (n & 7)) << 4));
                uint32_t r0, r1, r2, r3;
                ldsm_x4(addr, r0, r1, r2, r3);
                b[2 * p][0] = r0; b[2 * p + 1][0] = r1;
                b[2 * p][1] = r2; b[2 * p + 1][1] = r3;
            }
#pragma unroll
            for (int mt = 0; mt < 4; ++mt)
#pragma unroll
                for (int nt = 0; nt < 8; ++nt)
                    mma16816(acc[mt][nt][0], acc[mt][nt][1], acc[mt][nt][2], acc[mt][nt][3],
                             a[mt][0], a[mt][1], a[mt][2], a[mt][3],
                             b[nt][0], b[nt][1]);
        }
        __syncthreads();
    }

    // ---- epilogue part 1: zero-fill this CTA's latents block (replaces memset) ----
    {
        const float4 z = make_float4(0.f, 0.f, 0.f, 0.f);
        // BM x BN floats = 8192 float4; 256 threads -> 32 iterations, coalesced rows
#pragma unroll 4
        for (int i = tid; i < BM * (BN / 4); i += 256) {
            int row = i >> 5;            // BN/4 = 32 float4 per row
            int col4 = i & 31;
            *reinterpret_cast<float4*>(
                latents + (size_t)(m0 + row) * DSAE + n0 + col4 * 4) = z;
        }
    }

    // ---- epilogue part 2: bias + candidate extraction straight from registers ----
#pragma unroll
    for (int nt = 0; nt < 8; ++nt) {
        const int cA = n0 + wn * 64 + nt * 8 + 2 * (lane & 3);
        const float bA = __ldg(benc + cA);
        const float bB = __ldg(benc + cA + 1);
#pragma unroll
        for (int mt = 0; mt < 4; ++mt) {
            const int r0 = m0 + wm * 64 + mt * 16 + (lane >> 2);
            const int r1 = r0 + 8;
            push_cand(r0, cA,     acc[mt][nt][0] + bA);
            push_cand(r0, cA + 1, acc[mt][nt][1] + bB);
            push_cand(r1, cA,     acc[mt][nt][2] + bA);
            push_cand(r1, cA + 1, acc[mt][nt][3] + bB);
        }
    }
}

// ---------------------------------------------------------------------------
// Block-wide radix select helpers
// ---------------------------------------------------------------------------
__device__ __forceinline__ unsigned fkey(float f) {
    unsigned u = __float_as_uint(f);
    return (u & 0x80000000u) ? ~u : (u | 0x80000000u);
}

__device__ void radix_select_smem(const float* vals, int n, int k,
                                  unsigned* hist, unsigned* prefp, int* remp)
{
    const int tid = threadIdx.x;
    const int nth = blockDim.x;
    if (tid == 0) { *prefp = 0u; *remp = k; }
    __syncthreads();
    for (int lv = 3; lv >= 0; --lv) {
        for (int b = tid; b < 256; b += nth) hist[b] = 0u;
        __syncthreads();
        const unsigned pref = *prefp;
        const unsigned prefHi = (lv == 3) ? 0u : (pref >> ((lv + 1) * 8));
        const int shift = lv * 8;
        for (int i = tid; i < n; i += nth) {
            unsigned key = fkey(vals[i]);
            bool ok = (lv == 3) || ((key >> ((lv + 1) * 8)) == prefHi);
            if (ok) atomicAdd(&hist[(key >> shift) & 255u], 1u);
        }
        __syncthreads();
        if (tid == 0) {
            int rem = *remp;
            unsigned cum = 0;
            for (int b = 255; b >= 0; --b) {
                cum += hist[b];
                if ((int)cum >= rem) {
                    *prefp = pref | ((unsigned)b << shift);
                    *remp = rem - (int)(cum - hist[b]);
                    break;
                }
            }
        }
        __syncthreads();
    }
}

// ---------------------------------------------------------------------------
// Per-row: approx-top-64 among candidates -> exact fp32 recompute -> exact
// top-32 -> scatter into latents + compact topk lists. One block per row.
// ---------------------------------------------------------------------------
__global__ void __launch_bounds__(256)
sae_select(const float* __restrict__ x,
           const float* __restrict__ Wenc,
           const float* __restrict__ benc,
           float* __restrict__ latents)
{
    const int row = blockIdx.x;
    const int tid = threadIdx.x;
    const int wid = tid >> 5;
    const int lid = tid & 31;

    __shared__ float sval[CAND_MAX];
    __shared__ int   sidx[CAND_MAX];
    __shared__ float sx[DMODEL];
    __shared__ unsigned hist[256];
    __shared__ unsigned s_pref;
    __shared__ int s_rem, s_cnt, s_eq, s_taken;
    __shared__ int   sel_idx[REFINE_K];
    __shared__ float sel_val[REFINE_K];

    int cnt = g_cand_cnt[row];
    if (cnt > CAND_MAX) cnt = CAND_MAX;

    for (int i = tid; i < cnt; i += 256) {
        sval[i] = g_cand_val[(size_t)row * CAND_MAX + i];
        sidx[i] = g_cand_idx[(size_t)row * CAND_MAX + i];
    }
    for (int i = tid; i < DMODEL; i += 256) sx[i] = x[(size_t)row * DMODEL + i];
    __syncthreads();

    // --- Stage 1: approx top-K1 by bf16-GEMM value ---
    int K1 = (cnt < REFINE_K) ? cnt : REFINE_K;
    if (K1 > 0) radix_select_smem(sval, cnt, K1, hist, &s_pref, &s_rem);
    if (tid == 0) { s_cnt = 0; s_eq = 0; }
    __syncthreads();
    if (K1 > 0) {
        const unsigned T = s_pref;
        const int needEq = s_rem;
        for (int i = tid; i < cnt; i += 256) {
            unsigned key = fkey(sval[i]);
            if (key > T) {
                int slot = atomicAdd(&s_cnt, 1);
                sel_idx[slot] = sidx[i];
            } else if (key == T) {
                int e = atomicAdd(&s_eq, 1);
                if (e < needEq) {
                    int slot = atomicAdd(&s_cnt, 1);
                    sel_idx[slot] = sidx[i];
                }
            }
        }
    }
    __syncthreads();

    // --- Stage 2: exact fp32 recompute of the K1 selected candidates ---
    for (int j = wid; j < K1; j += 8) {
        const int s = sel_idx[j];
        const float* __restrict__ wr = Wenc + (size_t)s * DMODEL;
        float a = 0.0f;
#pragma unroll 6
        for (int kk = lid; kk < DMODEL; kk += 32)
            a = fmaf(sx[kk], wr[kk], a);
#pragma unroll
        for (int o = 16; o; o >>= 1) a += __shfl_xor_sync(0xFFFFFFFFu, a, o);
        if (lid == 0) sel_val[j] = a + benc[s];
    }
    __syncthreads();

    // --- Stage 3: exact top-32 among the K1 exact values ---
    int K2 = (K1 < TOPK) ? K1 : TOPK;
    if (K2 > 0) radix_select_smem(sel_val, K1, K2, hist, &s_pref, &s_rem);
    if (tid == 0) { s_taken = 0; s_eq = 0; }
    __syncthreads();
    if (K2 > 0) {
        const unsigned T2 = s_pref;
        const int needEq2 = s_rem;
        for (int i = tid; i < K1; i += 256) {
            float v = sel_val[i];
            unsigned key = fkey(v);
            bool take = false;
            if (key > T2) take = true;
            else if (key == T2) {
                int e = atomicAdd(&s_eq, 1);
                if (e < needEq2) take = true;
            }
            if (take) {
                int slot = atomicAdd(&s_taken, 1);
                int col = sel_idx[i];
                g_topk_idx[row * TOPK + slot] = col;
                g_topk_val[row * TOPK + slot] = v;
                latents[(size_t)row * DSAE + col] = v;
            }
        }
    }
    __syncthreads();
    if (tid >= s_taken && tid < TOPK) {      // defensive tail fill
        g_topk_idx[row * TOPK + tid] = 0;
        g_topk_val[row * TOPK + tid] = 0.0f;
    }
}

// ---------------------------------------------------------------------------
// Transpose W_dec [DMODEL, DSAE] -> g_wdecT [DSAE, DMODEL]
// ---------------------------------------------------------------------------
__global__ __launch_bounds__(256, 4)
void sae_transpose_wdec(const float* __restrict__ Wdec)
{
    __shared__ float t[32][33];
    const int tx = threadIdx.x;
    const int ty = threadIdx.y;
    const int s0 = blockIdx.x * 32;
    const int m0 = blockIdx.y * 32;

#pragma unroll
    for (int j = 0; j < 4; ++j) {
        int m = m0 + ty + j * 8;
        t[ty + j * 8][tx] = Wdec[(size_t)m * DSAE + s0 + tx];
    }
    __syncthreads();
#pragma unroll
    for (int j = 0; j < 4; ++j) {
        int s = s0 + ty + j * 8;
        g_wdecT[(size_t)s * DMODEL + m0 + tx] = t[tx][ty + j * 8];
    }
}

// ---------------------------------------------------------------------------
// Sparse decode: recon[b,m] = sum_k val_k * WdecT[idx_k][m]
// ---------------------------------------------------------------------------
__global__ __launch_bounds__(256, 4)
void sae_decode(float* __restrict__ recon)
{
    const int row = blockIdx.x;
    const int tid = threadIdx.x;

    __shared__ int   sidx[TOPK];
    __shared__ float sv[TOPK];
    if (tid < TOPK) {
        sidx[tid] = g_topk_idx[row * TOPK + tid];
        sv[tid]   = g_topk_val[row * TOPK + tid];
    }
    __syncthreads();

    float a0 = 0.0f, a1 = 0.0f, a2 = 0.0f;
#pragma unroll 8
    for (int k = 0; k < TOPK; ++k) {
        const float v = sv[k];
        const float* __restrict__ wr = g_wdecT + (size_t)sidx[k] * DMODEL;
        a0 = fmaf(v, wr[tid],       a0);
        a1 = fmaf(v, wr[tid + 256], a1);
        a2 = fmaf(v, wr[tid + 512], a2);
    }
    float* __restrict__ r = recon + (size_t)row * DMODEL;
    r[tid]       = a0;
    r[tid + 256] = a1;
    r[tid + 512] = a2;
}

// ---------------------------------------------------------------------------
// Launch
// ---------------------------------------------------------------------------
extern "C" void kernel_launch(void* const* d_in, const int* in_sizes, int n_in,
                              void* d_out, int out_size)
{
    const float* x    = (const float*)d_in[0];   // [8192, 768]
    const float* Wenc = (const float*)d_in[1];   // [24576, 768]
    const float* benc = (const float*)d_in[2];   // [24576]
    const float* Wdec = (const float*)d_in[3];   // [768, 24576]

    float* out     = (float*)d_out;
    float* recon   = out;
    float* latents = out + (size_t)BATCH * DMODEL;

    cudaFuncSetAttribute(sae_gemm_bf16, cudaFuncAttributeMaxDynamicSharedMemorySize,
                         SMEM_GEMM_BYTES);

    __nv_bfloat16 *xb_p = nullptr, *wb_p = nullptr;
    cudaGetSymbolAddress((void**)&xb_p, g_xb);
    cudaGetSymbolAddress((void**)&wb_p, g_wb);

    // 0) conversions + counter zero + W_dec transpose
    conv_to_bf16<<<4096, 256>>>(x, xb_p, (size_t)BATCH * DMODEL);
    conv_to_bf16<<<8192, 256>>>(Wenc, wb_p, (size_t)DSAE * DMODEL);
    zero_counts<<<BATCH / 256, 256>>>();
    sae_transpose_wdec<<<dim3(DSAE / 32, DMODEL / 32), dim3(32, 8)>>>(Wdec);

    // 1) bf16 HMMA GEMM: candidates + latents zero-fill fused
    sae_gemm_bf16<<<dim3(DSAE / BN, BATCH / BM), 256, SMEM_GEMM_BYTES>>>(
        xb_p, wb_p, benc, latents);

    // 2) exact select + scatter
    sae_select<<<BATCH, 256>>>(x, Wenc, benc, latents);

    // 3) sparse decode
    sae_decode<<<BATCH, 256>>>(recon);
}

// round 6
// speedup vs baseline: 3.3877x; 1.0532x over previous
#include <cuda_runtime.h>
#include <cuda_bf16.h>
#include <cstdint>

// Problem constants
#define BATCH   8192
#define DMODEL  768
#define DSAE    24576
#define TOPK    32

#define CAND_TH   2.0f
#define CAND_MAX  1024
#define REFINE_K  64

// ---------------------------------------------------------------------------
// Scratch (static __device__ globals; no allocation allowed)
// ---------------------------------------------------------------------------
__device__ __nv_bfloat16 g_xb[(size_t)BATCH * DMODEL];   // 12.6 MB
__device__ __nv_bfloat16 g_wb[(size_t)DSAE * DMODEL];    // 37.7 MB
__device__ float g_wdecT[(size_t)DSAE * DMODEL];         // 72 MB
__device__ int   g_cand_cnt[BATCH];
__device__ int   g_cand_idx[(size_t)BATCH * CAND_MAX];   // 33.5 MB
__device__ float g_cand_val[(size_t)BATCH * CAND_MAX];   // 33.5 MB
__device__ int   g_topk_idx[BATCH * TOPK];
__device__ float g_topk_val[BATCH * TOPK];

// ---------------------------------------------------------------------------
// PTX helpers (baseline ISA only: cp.async / ldmatrix / mma.sync)
// ---------------------------------------------------------------------------
__device__ __forceinline__ uint32_t smem_to_u32(const void* p) {
    uint32_t a;
    asm("{ .reg .u64 t; cvta.to.shared.u64 t, %1; cvt.u32.u64 %0, t; }" : "=r"(a) : "l"(p));
    return a;
}
#define CP_ASYNC16(s, g) \
    asm volatile("cp.async.cg.shared.global [%0], [%1], 16;" :: "r"(s), "l"(g))
#define CP_COMMIT()  asm volatile("cp.async.commit_group;" ::: "memory")
#define CP_WAIT(n)   asm volatile("cp.async.wait_group %0;" :: "n"(n) : "memory")

__device__ __forceinline__ void ldsm_x4(uint32_t addr, uint32_t& r0, uint32_t& r1,
                                        uint32_t& r2, uint32_t& r3)
{
    asm volatile("ldmatrix.sync.aligned.m8n8.x4.shared.b16 {%0,%1,%2,%3}, [%4];"
                 : "=r"(r0), "=r"(r1), "=r"(r2), "=r"(r3) : "r"(addr));
}
__device__ __forceinline__ void mma16816(float& d0, float& d1, float& d2, float& d3,
                                         uint32_t a0, uint32_t a1, uint32_t a2, uint32_t a3,
                                         uint32_t b0, uint32_t b1)
{
    asm volatile(
        "mma.sync.aligned.m16n8k16.row.col.f32.bf16.bf16.f32 "
        "{%0,%1,%2,%3}, {%4,%5,%6,%7}, {%8,%9}, {%0,%1,%2,%3};"
        : "+f"(d0), "+f"(d1), "+f"(d2), "+f"(d3)
        : "r"(a0), "r"(a1), "r"(a2), "r"(a3), "r"(b0), "r"(b1));
}

// ---------------------------------------------------------------------------
// Conversion / zero kernels
// ---------------------------------------------------------------------------
__global__ void conv_to_bf16(const float* __restrict__ src, __nv_bfloat16* __restrict__ dst,
                             size_t n)
{
    size_t i = (size_t)blockIdx.x * blockDim.x + threadIdx.x;
    size_t stride = (size_t)gridDim.x * blockDim.x;
    for (; i < n; i += stride) dst[i] = __float2bfloat16(src[i]);
}
__global__ void zero_counts()
{
    int i = blockIdx.x * blockDim.x + threadIdx.x;
    if (i < BATCH) g_cand_cnt[i] = 0;
}

// ---------------------------------------------------------------------------
// bf16 HMMA GEMM with fused candidate extraction + latents zero-fill.
// Block tile 128x128, K-chunks of 64. 512 threads = 16 warps (4M x 4N),
// warp tile 32x32. 3-stage cp.async smem pipeline + register double-buffered
// ldmatrix fragments.
// ---------------------------------------------------------------------------
#define BM 128
#define BN 128
#define BK 64
#define NCHUNKS (DMODEL / BK)          // 12
#define A_STAGE_BYTES (BM * 128)       // 16 KB
#define B_STAGE_BYTES (BN * 128)       // 16 KB
#define STAGE_BYTES   (A_STAGE_BYTES + B_STAGE_BYTES)   // 32 KB
#define NSTAGES 3
#define SMEM_GEMM_BYTES (NSTAGES * STAGE_BYTES)         // 96 KB

__device__ __forceinline__ void push_cand(int row, int col, float v)
{
    if (v > CAND_TH) {
        int pos = atomicAdd(&g_cand_cnt[row], 1);
        if (pos < CAND_MAX) {
            g_cand_idx[(size_t)row * CAND_MAX + pos] = col;
            g_cand_val[(size_t)row * CAND_MAX + pos] = v;
        }
    }
}

__global__ void __launch_bounds__(512)
sae_gemm_bf16(const __nv_bfloat16* __restrict__ xb,
              const __nv_bfloat16* __restrict__ wb,
              const float* __restrict__ benc,
              float* __restrict__ latents)
{
    extern __shared__ __align__(1024) char smem[];
    const uint32_t sb = smem_to_u32(smem);

    const int tid  = threadIdx.x;
    const int wid  = tid >> 5;
    const int lane = tid & 31;
    const int wm   = wid & 3;          // 0..3 (M, 32 rows each)
    const int wn   = wid >> 2;         // 0..3 (N, 32 cols each)
    const int n0   = blockIdx.x * BN;
    const int m0   = blockIdx.y * BM;

    const char* gA = (const char*)xb + (size_t)m0 * (DMODEL * 2);
    const char* gB = (const char*)wb + (size_t)n0 * (DMODEL * 2);

    float acc[2][4][4];
#pragma unroll
    for (int i = 0; i < 2; ++i)
#pragma unroll
        for (int j = 0; j < 4; ++j)
#pragma unroll
            for (int q = 0; q < 4; ++q) acc[i][j][q] = 0.0f;

    // ---- async tile loader (chunk c -> stage st) ----
    auto load_tiles = [&](int c, int st) {
        const int ktb = c * (BK * 2);            // k byte offset in gmem row
        const uint32_t sa = sb + st * STAGE_BYTES;
        const uint32_t sB = sa + A_STAGE_BYTES;
        // A: 128 rows x 8 chunks of 16B = 1024 -> 2 per thread
#pragma unroll
        for (int q = 0; q < 2; ++q) {
            int i = tid + q * 512;
            int row = i >> 3, cc = i & 7;
            uint32_t soff = (uint32_t)(row * 128 + ((cc ^ (row & 7)) << 4));
            CP_ASYNC16(sa + soff, gA + (size_t)row * (DMODEL * 2) + ktb + cc * 16);
        }
        // B: 128 rows x 8 chunks = 1024 -> 2 per thread
#pragma unroll
        for (int q = 0; q < 2; ++q) {
            int i = tid + q * 512;
            int row = i >> 3, cc = i & 7;
            uint32_t soff = (uint32_t)(row * 128 + ((cc ^ (row & 7)) << 4));
            CP_ASYNC16(sB + soff, gB + (size_t)row * (DMODEL * 2) + ktb + cc * 16);
        }
    };

    // Fragment buffers (double-buffered across k16 steps)
    uint32_t aF[2][2][4];   // [buf][mt][reg]
    uint32_t bF[2][4][2];   // [buf][nt][reg]

    auto load_frag = [&](int buf, int ks, uint32_t sa, uint32_t sB) {
        const int chunk = 2 * ks + (lane >> 4);
#pragma unroll
        for (int mt = 0; mt < 2; ++mt) {
            int m = wm * 32 + mt * 16 + (lane & 15);
            uint32_t addr = sa + (uint32_t)(m * 128 + ((chunk ^ (m & 7)) << 4));
            ldsm_x4(addr, aF[buf][mt][0], aF[buf][mt][1], aF[buf][mt][2], aF[buf][mt][3]);
        }
#pragma unroll
        for (int p = 0; p < 2; ++p) {
            int n = wn * 32 + p * 16 + (lane & 15);
            uint32_t addr = sB + (uint32_t)(n * 128 + ((chunk ^ (n & 7)) << 4));
            uint32_t r0, r1, r2, r3;
            ldsm_x4(addr, r0, r1, r2, r3);
            bF[buf][2 * p][0] = r0; bF[buf][2 * p + 1][0] = r1;
            bF[buf][2 * p][1] = r2; bF[buf][2 * p + 1][1] = r3;
        }
    };

    // prologue: stages 0,1
    load_tiles(0, 0);
    CP_COMMIT();
    load_tiles(1, 1);
    CP_COMMIT();

    for (int c = 0; c < NCHUNKS; ++c) {
        if (c + 2 < NCHUNKS) {
            load_tiles(c + 2, (c + 2) % NSTAGES);
            CP_COMMIT();
            CP_WAIT(2);
        } else if (c + 2 == NCHUNKS) {
            CP_WAIT(1);
        } else {
            CP_WAIT(0);
        }
        __syncthreads();

        const uint32_t sa = sb + (c % NSTAGES) * STAGE_BYTES;
        const uint32_t sB = sa + A_STAGE_BYTES;

        load_frag(0, 0, sa, sB);
#pragma unroll
        for (int ks = 0; ks < 4; ++ks) {
            if (ks < 3) load_frag((ks + 1) & 1, ks + 1, sa, sB);
            const int cur = ks & 1;
#pragma unroll
            for (int mt = 0; mt < 2; ++mt)
#pragma unroll
                for (int nt = 0; nt < 4; ++nt)
                    mma16816(acc[mt][nt][0], acc[mt][nt][1], acc[mt][nt][2], acc[mt][nt][3],
                             aF[cur][mt][0], aF[cur][mt][1], aF[cur][mt][2], aF[cur][mt][3],
                             bF[cur][nt][0], bF[cur][nt][1]);
        }
        __syncthreads();
    }

    // ---- epilogue part 1: zero-fill this CTA's latents block (replaces memset) ----
    {
        const float4 z = make_float4(0.f, 0.f, 0.f, 0.f);
        // BM x BN floats = 4096 float4; 512 threads -> 8 iterations
#pragma unroll
        for (int q = 0; q < (BM * BN / 4) / 512; ++q) {
            int i = tid + q * 512;
            int row = i >> 5;            // BN/4 = 32 float4 per row
            int col4 = i & 31;
            *reinterpret_cast<float4*>(
                latents + (size_t)(m0 + row) * DSAE + n0 + col4 * 4) = z;
        }
    }

    // ---- epilogue part 2: bias + candidate extraction straight from registers ----
#pragma unroll
    for (int nt = 0; nt < 4; ++nt) {
        const int cA = n0 + wn * 32 + nt * 8 + 2 * (lane & 3);
        const float bA = __ldg(benc + cA);
        const float bB = __ldg(benc + cA + 1);
#pragma unroll
        for (int mt = 0; mt < 2; ++mt) {
            const int r0 = m0 + wm * 32 + mt * 16 + (lane >> 2);
            const int r1 = r0 + 8;
            push_cand(r0, cA,     acc[mt][nt][0] + bA);
            push_cand(r0, cA + 1, acc[mt][nt][1] + bB);
            push_cand(r1, cA,     acc[mt][nt][2] + bA);
            push_cand(r1, cA + 1, acc[mt][nt][3] + bB);
        }
    }
}

// ---------------------------------------------------------------------------
// Block-wide radix select helpers
// ---------------------------------------------------------------------------
__device__ __forceinline__ unsigned fkey(float f) {
    unsigned u = __float_as_uint(f);
    return (u & 0x80000000u) ? ~u : (u | 0x80000000u);
}

__device__ void radix_select_smem(const float* vals, int n, int k,
                                  unsigned* hist, unsigned* prefp, int* remp)
{
    const int tid = threadIdx.x;
    const int nth = blockDim.x;
    if (tid == 0) { *prefp = 0u; *remp = k; }
    __syncthreads();
    for (int lv = 3; lv >= 0; --lv) {
        for (int b = tid; b < 256; b += nth) hist[b] = 0u;
        __syncthreads();
        const unsigned pref = *prefp;
        const unsigned prefHi = (lv == 3) ? 0u : (pref >> ((lv + 1) * 8));
        const int shift = lv * 8;
        for (int i = tid; i < n; i += nth) {
            unsigned key = fkey(vals[i]);
            bool ok = (lv == 3) || ((key >> ((lv + 1) * 8)) == prefHi);
            if (ok) atomicAdd(&hist[(key >> shift) & 255u], 1u);
        }
        __syncthreads();
        if (tid == 0) {
            int rem = *remp;
            unsigned cum = 0;
            for (int b = 255; b >= 0; --b) {
                cum += hist[b];
                if ((int)cum >= rem) {
                    *prefp = pref | ((unsigned)b << shift);
                    *remp = rem - (int)(cum - hist[b]);
                    break;
                }
            }
        }
        __syncthreads();
    }
}

// ---------------------------------------------------------------------------
// Per-row: approx-top-64 among candidates -> exact fp32 recompute -> exact
// top-32 -> scatter into latents + compact topk lists. One block per row.
// ---------------------------------------------------------------------------
__global__ void __launch_bounds__(256)
sae_select(const float* __restrict__ x,
           const float* __restrict__ Wenc,
           const float* __restrict__ benc,
           float* __restrict__ latents)
{
    const int row = blockIdx.x;
    const int tid = threadIdx.x;
    const int wid = tid >> 5;
    const int lid = tid & 31;

    __shared__ float sval[CAND_MAX];
    __shared__ int   sidx[CAND_MAX];
    __shared__ float sx[DMODEL];
    __shared__ unsigned hist[256];
    __shared__ unsigned s_pref;
    __shared__ int s_rem, s_cnt, s_eq, s_taken;
    __shared__ int   sel_idx[REFINE_K];
    __shared__ float sel_val[REFINE_K];

    int cnt = g_cand_cnt[row];
    if (cnt > CAND_MAX) cnt = CAND_MAX;

    for (int i = tid; i < cnt; i += 256) {
        sval[i] = g_cand_val[(size_t)row * CAND_MAX + i];
        sidx[i] = g_cand_idx[(size_t)row * CAND_MAX + i];
    }
    for (int i = tid; i < DMODEL; i += 256) sx[i] = x[(size_t)row * DMODEL + i];
    __syncthreads();

    // --- Stage 1: approx top-K1 by bf16-GEMM value ---
    int K1 = (cnt < REFINE_K) ? cnt : REFINE_K;
    if (K1 > 0) radix_select_smem(sval, cnt, K1, hist, &s_pref, &s_rem);
    if (tid == 0) { s_cnt = 0; s_eq = 0; }
    __syncthreads();
    if (K1 > 0) {
        const unsigned T = s_pref;
        const int needEq = s_rem;
        for (int i = tid; i < cnt; i += 256) {
            unsigned key = fkey(sval[i]);
            if (key > T) {
                int slot = atomicAdd(&s_cnt, 1);
                sel_idx[slot] = sidx[i];
            } else if (key == T) {
                int e = atomicAdd(&s_eq, 1);
                if (e < needEq) {
                    int slot = atomicAdd(&s_cnt, 1);
                    sel_idx[slot] = sidx[i];
                }
            }
        }
    }
    __syncthreads();

    // --- Stage 2: exact fp32 recompute of the K1 selected candidates ---
    for (int j = wid; j < K1; j += 8) {
        const int s = sel_idx[j];
        const float* __restrict__ wr = Wenc + (size_t)s * DMODEL;
        float a = 0.0f;
#pragma unroll 6
        for (int kk = lid; kk < DMODEL; kk += 32)
            a = fmaf(sx[kk], wr[kk], a);
#pragma unroll
        for (int o = 16; o; o >>= 1) a += __shfl_xor_sync(0xFFFFFFFFu, a, o);
        if (lid == 0) sel_val[j] = a + benc[s];
    }
    __syncthreads();

    // --- Stage 3: exact top-32 among the K1 exact values ---
    int K2 = (K1 < TOPK) ? K1 : TOPK;
    if (K2 > 0) radix_select_smem(sel_val, K1, K2, hist, &s_pref, &s_rem);
    if (tid == 0) { s_taken = 0; s_eq = 0; }
    __syncthreads();
    if (K2 > 0) {
        const unsigned T2 = s_pref;
        const int needEq2 = s_rem;
        for (int i = tid; i < K1; i += 256) {
            float v = sel_val[i];
            unsigned key = fkey(v);
            bool take = false;
            if (key > T2) take = true;
            else if (key == T2) {
                int e = atomicAdd(&s_eq, 1);
                if (e < needEq2) take = true;
            }
            if (take) {
                int slot = atomicAdd(&s_taken, 1);
                int col = sel_idx[i];
                g_topk_idx[row * TOPK + slot] = col;
                g_topk_val[row * TOPK + slot] = v;
                latents[(size_t)row * DSAE + col] = v;
            }
        }
    }
    __syncthreads();
    if (tid >= s_taken && tid < TOPK) {      // defensive tail fill
        g_topk_idx[row * TOPK + tid] = 0;
        g_topk_val[row * TOPK + tid] = 0.0f;
    }
}

// ---------------------------------------------------------------------------
// Transpose W_dec [DMODEL, DSAE] -> g_wdecT [DSAE, DMODEL]
// ---------------------------------------------------------------------------
__global__ __launch_bounds__(256, 4)
void sae_transpose_wdec(const float* __restrict__ Wdec)
{
    __shared__ float t[32][33];
    const int tx = threadIdx.x;
    const int ty = threadIdx.y;
    const int s0 = blockIdx.x * 32;
    const int m0 = blockIdx.y * 32;

#pragma unroll
    for (int j = 0; j < 4; ++j) {
        int m = m0 + ty + j * 8;
        t[ty + j * 8][tx] = Wdec[(size_t)m * DSAE + s0 + tx];
    }
    __syncthreads();
#pragma unroll
    for (int j = 0; j < 4; ++j) {
        int s = s0 + ty + j * 8;
        g_wdecT[(size_t)s * DMODEL + m0 + tx] = t[tx][ty + j * 8];
    }
}

// ---------------------------------------------------------------------------
// Sparse decode: recon[b,m] = sum_k val_k * WdecT[idx_k][m]
// ---------------------------------------------------------------------------
__global__ __launch_bounds__(256, 4)
void sae_decode(float* __restrict__ recon)
{
    const int row = blockIdx.x;
    const int tid = threadIdx.x;

    __shared__ int   sidx[TOPK];
    __shared__ float sv[TOPK];
    if (tid < TOPK) {
        sidx[tid] = g_topk_idx[row * TOPK + tid];
        sv[tid]   = g_topk_val[row * TOPK + tid];
    }
    __syncthreads();

    float a0 = 0.0f, a1 = 0.0f, a2 = 0.0f;
#pragma unroll 8
    for (int k = 0; k < TOPK; ++k) {
        const float v = sv[k];
        const float* __restrict__ wr = g_wdecT + (size_t)sidx[k] * DMODEL;
        a0 = fmaf(v, wr[tid],       a0);
        a1 = fmaf(v, wr[tid + 256], a1);
        a2 = fmaf(v, wr[tid + 512], a2);
    }
    float* __restrict__ r = recon + (size_t)row * DMODEL;
    r[tid]       = a0;
    r[tid + 256] = a1;
    r[tid + 512] = a2;
}

// ---------------------------------------------------------------------------
// Launch
// ---------------------------------------------------------------------------
extern "C" void kernel_launch(void* const* d_in, const int* in_sizes, int n_in,
                              void* d_out, int out_size)
{
    const float* x    = (const float*)d_in[0];   // [8192, 768]
    const float* Wenc = (const float*)d_in[1];   // [24576, 768]
    const float* benc = (const float*)d_in[2];   // [24576]
    const float* Wdec = (const float*)d_in[3];   // [768, 24576]

    float* out     = (float*)d_out;
    float* recon   = out;
    float* latents = out + (size_t)BATCH * DMODEL;

    cudaFuncSetAttribute(sae_gemm_bf16, cudaFuncAttributeMaxDynamicSharedMemorySize,
                         SMEM_GEMM_BYTES);

    __nv_bfloat16 *xb_p = nullptr, *wb_p = nullptr;
    cudaGetSymbolAddress((void**)&xb_p, g_xb);
    cudaGetSymbolAddress((void**)&wb_p, g_wb);

    // 0) conversions + counter zero + W_dec transpose
    conv_to_bf16<<<4096, 256>>>(x, xb_p, (size_t)BATCH * DMODEL);
    conv_to_bf16<<<8192, 256>>>(Wenc, wb_p, (size_t)DSAE * DMODEL);
    zero_counts<<<BATCH / 256, 256>>>();
    sae_transpose_wdec<<<dim3(DSAE / 32, DMODEL / 32), dim3(32, 8)>>>(Wdec);

    // 1) bf16 HMMA GEMM: candidates + latents zero-fill fused
    sae_gemm_bf16<<<dim3(DSAE / BN, BATCH / BM), 512, SMEM_GEMM_BYTES>>>(
        xb_p, wb_p, benc, latents);

    // 2) exact select + scatter
    sae_select<<<BATCH, 256>>>(x, Wenc, benc, latents);

    // 3) sparse decode
    sae_decode<<<BATCH, 256>>>(recon);
}